// round 1
// baseline (speedup 1.0000x reference)
#include <cuda_runtime.h>
#include <stdint.h>

// Problem shape (fixed by the reference setup_inputs):
//   pointclouds: (32, 131072, 6) f32, task_transform: (32, 4, 4) f32
// Semantics: per batch, stable-partition rows by validity; valid rows (original
// 6-float values) first in original order, remaining rows zero.

#define BATCH 32
#define NPTS 131072
#define PTS_PER_BLOCK 2048
#define NBLK (NPTS / PTS_PER_BLOCK)        // 64 blocks per batch
#define THREADS 256
#define ITEMS (PTS_PER_BLOCK / THREADS)    // 8
#define WORDS_PER_BLOCK (PTS_PER_BLOCK / 32) // 64
#define FLAG_WORDS (NPTS / 32)             // 4096

// Scratch (allocation-free rule: __device__ globals)
__device__ unsigned int g_flags[BATCH * FLAG_WORDS];
__device__ int g_blockCounts[BATCH * NBLK];
__device__ int g_blockOffsets[BATCH * NBLK];
__device__ int g_total[BATCH];

// ---------------------------------------------------------------------------
// K1: compute validity flags (bitmask) + per-block valid counts.
// Striped access: warp lane l handles 32 consecutive points -> ballot = flag word.
// ---------------------------------------------------------------------------
__global__ void __launch_bounds__(THREADS) k_flags(
    const float* __restrict__ pc, const float* __restrict__ tt)
{
    const int b   = blockIdx.y;
    const int blk = blockIdx.x;
    const int tid = threadIdx.x;
    const int lane = tid & 31, warp = tid >> 5;

    __shared__ float T[16];
    __shared__ int scount;
    if (tid < 16) T[tid] = tt[b * 16 + tid];
    if (tid == 0) scount = 0;
    __syncthreads();

    // p[e] = x*rot[0][e] + y*rot[1][e] + z*rot[2][e] + trans[e]
    // rot[d][e] = tt[d*4+e], trans[e] = tt[e*4+3]
    const float r00 = T[0],  r01 = T[1],  r02 = T[2],  tx = T[3];
    const float r10 = T[4],  r11 = T[5],  r12 = T[6],  ty = T[7];
    const float r20 = T[8],  r21 = T[9],  r22 = T[10], tz = T[11];

    const float* base = pc + (size_t)b * NPTS * 6;
    const int p0 = blk * PTS_PER_BLOCK;
    int cnt = 0;

#pragma unroll
    for (int i = 0; i < ITEMS; i++) {
        const int idx = p0 + i * THREADS + tid;
        const float2* row = (const float2*)(base + (size_t)idx * 6);
        const float2 a = row[0];   // x, y
        const float2 m1 = row[1];  // z, nx
        const float2 m2 = row[2];  // ny, nz
        const float x = a.x, y = a.y, z = m1.x;
        const float nsum = m1.y + m2.x + m2.y;

        const float px = x * r00 + y * r10 + z * r20 + tx;
        const float py = x * r01 + y * r11 + z * r21 + ty;
        const float pz = x * r02 + y * r12 + z * r22 + tz;

        const bool v = (px * px + py * py < 1.0f) && (pz < 1.0f) && (nsum != 0.0f);
        const unsigned m = __ballot_sync(0xffffffffu, v);
        if (lane == 0) {
            g_flags[b * FLAG_WORDS + (p0 >> 5) + i * (THREADS / 32) + warp] = m;
            cnt += __popc(m);
        }
    }
    if (lane == 0) atomicAdd(&scount, cnt);
    __syncthreads();
    if (tid == 0) g_blockCounts[b * NBLK + blk] = scount;
}

// ---------------------------------------------------------------------------
// K2: per-batch exclusive scan over the 64 block counts. 32 blocks x 64 thr.
// ---------------------------------------------------------------------------
__global__ void __launch_bounds__(NBLK) k_scan()
{
    const int b = blockIdx.x;
    const int t = threadIdx.x;
    __shared__ int s[NBLK];
    const int c = g_blockCounts[b * NBLK + t];
    s[t] = c;
    __syncthreads();
#pragma unroll
    for (int off = 1; off < NBLK; off <<= 1) {
        const int v = (t >= off) ? s[t - off] : 0;
        __syncthreads();
        s[t] += v;
        __syncthreads();
    }
    g_blockOffsets[b * NBLK + t] = s[t] - c;   // exclusive
    if (t == NBLK - 1) g_total[b] = s[t];
}

// ---------------------------------------------------------------------------
// K3: zero the tail region [total[b], NPTS) per batch. Disjoint from K4 writes.
// ---------------------------------------------------------------------------
__global__ void __launch_bounds__(THREADS) k_zero(float* __restrict__ out)
{
    const int b = blockIdx.y;
    const int blk = blockIdx.x;
    const int tid = threadIdx.x;
    const int total = g_total[b];
    float* dst = out + (size_t)b * NPTS * 6;
    const float2 z = make_float2(0.0f, 0.0f);
#pragma unroll
    for (int i = 0; i < ITEMS; i++) {
        const int row = blk * PTS_PER_BLOCK + i * THREADS + tid;
        if (row >= total) {
            float2* o = (float2*)(dst + (size_t)row * 6);
            o[0] = z; o[1] = z; o[2] = z;
        }
    }
}

// ---------------------------------------------------------------------------
// K4: stable scatter. Read bitmask, compute in-block ranks via word-prefix
// scan + popc, gather only valid rows and write to base+rank.
// ---------------------------------------------------------------------------
__global__ void __launch_bounds__(THREADS) k_scatter(
    const float* __restrict__ pc, float* __restrict__ out)
{
    const int b = blockIdx.y;
    const int blk = blockIdx.x;
    const int tid = threadIdx.x;

    __shared__ unsigned sw[WORDS_PER_BLOCK];
    __shared__ int s[WORDS_PER_BLOCK];   // inclusive popc scan
    __shared__ int sbase;

    if (tid < WORDS_PER_BLOCK) {
        const unsigned m = g_flags[b * FLAG_WORDS + blk * WORDS_PER_BLOCK + tid];
        sw[tid] = m;
        s[tid] = __popc(m);
    }
    if (tid == 0) sbase = g_blockOffsets[b * NBLK + blk];
    __syncthreads();
#pragma unroll
    for (int off = 1; off < WORDS_PER_BLOCK; off <<= 1) {
        int v = 0;
        if (tid < WORDS_PER_BLOCK && tid >= off) v = s[tid - off];
        __syncthreads();
        if (tid < WORDS_PER_BLOCK) s[tid] += v;
        __syncthreads();
    }

    const float* src = pc + (size_t)b * NPTS * 6;
    float* dst = out + (size_t)b * NPTS * 6;
    const int base = sbase;

#pragma unroll
    for (int i = 0; i < ITEMS; i++) {
        const int l = i * THREADS + tid;            // local point index
        const unsigned m = sw[l >> 5];
        const int bit = l & 31;
        if ((m >> bit) & 1u) {
            const int rank = s[l >> 5] - __popc(m) + __popc(m & ((1u << bit) - 1u));
            const int idx = blk * PTS_PER_BLOCK + l;
            const float2* row = (const float2*)(src + (size_t)idx * 6);
            const float2 a = row[0], c = row[1], d = row[2];
            float2* o = (float2*)(dst + (size_t)(base + rank) * 6);
            o[0] = a; o[1] = c; o[2] = d;
        }
    }
}

// ---------------------------------------------------------------------------
extern "C" void kernel_launch(void* const* d_in, const int* in_sizes, int n_in,
                              void* d_out, int out_size)
{
    const float* pc = (const float*)d_in[0];   // (32, 131072, 6)
    const float* tt = (const float*)d_in[1];   // (32, 4, 4)
    float* out = (float*)d_out;                // (32, 131072, 6)

    dim3 grid(NBLK, BATCH);
    k_flags<<<grid, THREADS>>>(pc, tt);
    k_scan<<<BATCH, NBLK>>>();
    k_zero<<<grid, THREADS>>>(out);
    k_scatter<<<grid, THREADS>>>(pc, out);
}

// round 6
// speedup vs baseline: 1.5227x; 1.5227x over previous
#include <cuda_runtime.h>
#include <stdint.h>

// pointclouds: (32, 131072, 6) f32, task_transform: (32, 4, 4) f32
// Stable-partition each batch: valid rows (original values, original order)
// first, rest zero.

#define BATCH 32
#define NPTS 131072
#define TILE 2048
#define NTILES (NPTS / TILE)            // 64
#define THREADS 256
#define ITEMS (TILE / THREADS)          // 8
#define WORDS (TILE / 32)               // 64 flag words per tile

#define FLAG_AGG 0x40000000u
#define FLAG_INC 0x80000000u
#define VAL_MASK 0x00FFFFFFu

__device__ unsigned int g_state[BATCH * NTILES];

// ---------------------------------------------------------------------------
// K0: reset lookback tile states (runs inside the graph on every replay).
// ---------------------------------------------------------------------------
__global__ void k_init()
{
    for (int i = blockIdx.x * blockDim.x + threadIdx.x;
         i < BATCH * NTILES; i += gridDim.x * blockDim.x)
        g_state[i] = 0u;
}

// ---------------------------------------------------------------------------
// K1: single-pass stable compaction + fused tail zeroing.
// grid (NTILES, BATCH), 256 threads.
// ---------------------------------------------------------------------------
__global__ void __launch_bounds__(THREADS) k_compact(
    const float* __restrict__ pc, const float* __restrict__ tt,
    float* __restrict__ out)
{
    const int b    = blockIdx.y;
    const int tile = blockIdx.x;
    const int tid  = threadIdx.x;
    const int lane = tid & 31, warp = tid >> 5;

    __shared__ float T[12];
    __shared__ unsigned sw[WORDS];
    __shared__ int sscan[WORDS];     // inclusive popc scan
    __shared__ int sbase;

    if (tid < 12) T[tid] = tt[b * 16 + tid];
    __syncthreads();

    const float r00 = T[0],  r01 = T[1],  r02 = T[2],  tx = T[3];
    const float r10 = T[4],  r11 = T[5],  r12 = T[6],  ty = T[7];
    const float r20 = T[8],  r21 = T[9],  r22 = T[10], tz = T[11];

    const float* src = pc + (size_t)b * NPTS * 6;
    const int p0 = tile * TILE;

    // --- flags: warp w, iter i covers points [p0 + i*256 + w*32, +32) ---
#pragma unroll
    for (int i = 0; i < ITEMS; i++) {
        const int idx = p0 + i * THREADS + tid;
        const float2* row = (const float2*)(src + (size_t)idx * 6);
        const float2 a  = row[0];   // x, y
        const float2 m1 = row[1];   // z, nx
        const float2 m2 = row[2];   // ny, nz
        const float x = a.x, y = a.y, z = m1.x;
        const float nsum = m1.y + m2.x + m2.y;

        const float px = x * r00 + y * r10 + z * r20 + tx;
        const float py = x * r01 + y * r11 + z * r21 + ty;
        const float pz = x * r02 + y * r12 + z * r22 + tz;

        const bool v = (px * px + py * py < 1.0f) && (pz < 1.0f) && (nsum != 0.0f);
        const unsigned m = __ballot_sync(0xffffffffu, v);
        if (lane == 0) sw[i * (THREADS / 32) + warp] = m;
    }
    __syncthreads();

    // --- inclusive scan of the 64 word popcounts (2 warps) ---
    if (tid < WORDS) {
        int v = __popc(sw[tid]);
#pragma unroll
        for (int off = 1; off < 32; off <<= 1) {
            const int n = __shfl_up_sync(0xffffffffu, v, off);
            if ((tid & 31) >= off) v += n;
        }
        sscan[tid] = v;
    }
    __syncthreads();
    if (tid >= 32 && tid < WORDS) sscan[tid] += sscan[31];
    __syncthreads();

    const int cnt = sscan[WORDS - 1];

    // --- decoupled lookback (thread 0) ---
    if (tid == 0) {
        unsigned* st = &g_state[b * NTILES + tile];
        if (tile == 0) {
            atomicExch(st, FLAG_INC | (unsigned)cnt);
            sbase = 0;
        } else {
            atomicExch(st, FLAG_AGG | (unsigned)cnt);   // publish aggregate first
            int run = 0;
            int p = tile - 1;
            for (;;) {
                unsigned v;
                do { v = atomicAdd(&g_state[b * NTILES + p], 0u); }
                while ((v & (FLAG_AGG | FLAG_INC)) == 0u);
                run += (int)(v & VAL_MASK);
                if (v & FLAG_INC) break;
                p--;
            }
            sbase = run;
            atomicExch(st, FLAG_INC | (unsigned)(run + cnt));
        }
    }
    __syncthreads();

    const int base = sbase;
    float* dst = out + (size_t)b * NPTS * 6;

    // --- dense stable write: thread j handles the j-th valid row ---
    for (int j = tid; j < cnt; j += THREADS) {
        // smallest w with sscan[w] > j
        int lo = 0, hi = WORDS - 1;
#pragma unroll
        for (int s = 0; s < 6; s++) {
            const int mid = (lo + hi) >> 1;
            if (sscan[mid] > j) hi = mid; else lo = mid + 1;
        }
        const int w = lo;
        const int prior = w ? sscan[w - 1] : 0;
        const int r = j - prior;
        const int bit = __fns(sw[w], 0, r + 1);
        const int idx = p0 + w * 32 + bit;

        const float2* row = (const float2*)(src + (size_t)idx * 6);  // L2 hit
        const float2 a = row[0], c = row[1], d = row[2];
        float2* o = (float2*)(dst + (size_t)(base + j) * 6);
        o[0] = a; o[1] = c; o[2] = d;
    }

    // --- fused tail zeroing ---
    // Exclusive invalid-prefix of this tile = p0 - base; this tile's invalid
    // count = TILE - cnt. Zero output rows
    // [NPTS - inv_prefix - inv, NPTS - inv_prefix); disjoint across tiles,
    // union = [total, NPTS).
    const int inv = TILE - cnt;
    if (inv > 0) {
        const int inv_prefix = p0 - base;
        const int row0 = NPTS - inv_prefix - inv;
        float2* z2 = (float2*)(dst + (size_t)row0 * 6);
        const int n2 = inv * 3;                  // float2 count
        const float2 z = make_float2(0.0f, 0.0f);
        for (int i = tid; i < n2; i += THREADS) z2[i] = z;
    }
}

// ---------------------------------------------------------------------------
extern "C" void kernel_launch(void* const* d_in, const int* in_sizes, int n_in,
                              void* d_out, int out_size)
{
    const float* pc = (const float*)d_in[0];   // (32, 131072, 6)
    const float* tt = (const float*)d_in[1];   // (32, 4, 4)
    float* out = (float*)d_out;

    k_init<<<8, THREADS>>>();
    dim3 gc(NTILES, BATCH);
    k_compact<<<gc, THREADS>>>(pc, tt, out);
}

// round 7
// speedup vs baseline: 1.5940x; 1.0468x over previous
#include <cuda_runtime.h>
#include <stdint.h>

// pointclouds: (32, 131072, 6) f32, task_transform: (32, 4, 4) f32
// Stable-partition each batch: valid rows (original values, original order)
// first, rest zero.

#define BATCH 32
#define NPTS 131072
#define TILE 2048
#define NTILES (NPTS / TILE)            // 64
#define THREADS 256
#define ITEMS (TILE / THREADS)          // 8
#define WORDS (TILE / 32)               // 64 flag words per tile

#define FLAG_AGG 0x40000000u
#define FLAG_INC 0x80000000u
#define VAL_MASK 0x00FFFFFFu

__device__ unsigned int g_state[BATCH * NTILES];

// ---------------------------------------------------------------------------
// K0: reset lookback tile states (runs inside the graph on every replay).
// ---------------------------------------------------------------------------
__global__ void k_init()
{
    for (int i = blockIdx.x * blockDim.x + threadIdx.x;
         i < BATCH * NTILES; i += gridDim.x * blockDim.x)
        g_state[i] = 0u;
}

// ---------------------------------------------------------------------------
// K1: single-pass stable compaction + fused tail zeroing.
// grid (NTILES, BATCH), 256 threads.
// ---------------------------------------------------------------------------
__global__ void __launch_bounds__(THREADS) k_compact(
    const float* __restrict__ pc, const float* __restrict__ tt,
    float* __restrict__ out)
{
    const int b    = blockIdx.y;
    const int tile = blockIdx.x;
    const int tid  = threadIdx.x;
    const int lane = tid & 31, warp = tid >> 5;

    __shared__ float T[12];
    __shared__ unsigned sw[WORDS];
    __shared__ int sscan[WORDS];     // inclusive popc scan
    __shared__ int sbase;

    if (tid < 12) T[tid] = tt[b * 16 + tid];
    __syncthreads();

    const float r00 = T[0],  r01 = T[1],  r02 = T[2],  tx = T[3];
    const float r10 = T[4],  r11 = T[5],  r12 = T[6],  ty = T[7];
    const float r20 = T[8],  r21 = T[9],  r22 = T[10], tz = T[11];

    const float* src = pc + (size_t)b * NPTS * 6;
    const int p0 = tile * TILE;

    // --- flags: warp w, iter i covers points [p0 + i*256 + w*32, +32) ---
#pragma unroll
    for (int i = 0; i < ITEMS; i++) {
        const int idx = p0 + i * THREADS + tid;
        const float2* row = (const float2*)(src + (size_t)idx * 6);
        const float2 a  = row[0];   // x, y
        const float2 m1 = row[1];   // z, nx
        const float2 m2 = row[2];   // ny, nz
        const float x = a.x, y = a.y, z = m1.x;
        const float nsum = m1.y + m2.x + m2.y;

        const float px = x * r00 + y * r10 + z * r20 + tx;
        const float py = x * r01 + y * r11 + z * r21 + ty;
        const float pz = x * r02 + y * r12 + z * r22 + tz;

        const bool v = (px * px + py * py < 1.0f) && (pz < 1.0f) && (nsum != 0.0f);
        const unsigned m = __ballot_sync(0xffffffffu, v);
        if (lane == 0) sw[i * (THREADS / 32) + warp] = m;
    }
    __syncthreads();

    // --- inclusive scan of the 64 word popcounts (2 warps) ---
    if (tid < WORDS) {
        int v = __popc(sw[tid]);
#pragma unroll
        for (int off = 1; off < 32; off <<= 1) {
            const int n = __shfl_up_sync(0xffffffffu, v, off);
            if ((tid & 31) >= off) v += n;
        }
        sscan[tid] = v;
    }
    __syncthreads();
    if (tid >= 32 && tid < WORDS) sscan[tid] += sscan[31];
    __syncthreads();

    const int cnt = sscan[WORDS - 1];

    // --- warp-parallel decoupled lookback (warp 0) ---
    if (tid < 32) {
        unsigned* stArr = &g_state[b * NTILES];
        if (tile == 0) {
            if (lane == 0) {
                atomicExch(&stArr[0], FLAG_INC | (unsigned)cnt);
                sbase = 0;
            }
        } else {
            if (lane == 0) atomicExch(&stArr[tile], FLAG_AGG | (unsigned)cnt);
            int run = 0;
            int p = tile - 1 - lane;       // lane 0 = nearest predecessor
            for (;;) {
                unsigned v;
                if (p >= 0) {
                    do { v = *(volatile unsigned*)&stArr[p]; }
                    while ((v & (FLAG_AGG | FLAG_INC)) == 0u);
                } else {
                    v = FLAG_INC;          // virtual tile -1 with prefix 0
                }
                const unsigned incs =
                    __ballot_sync(0xffffffffu, (v & FLAG_INC) != 0u);
                int contrib;
                if (incs) {
                    const int L = __ffs(incs) - 1;   // nearest INC
                    contrib = (lane <= L) ? (int)(v & VAL_MASK) : 0;
                } else {
                    contrib = (int)(v & VAL_MASK);
                }
#pragma unroll
                for (int o = 16; o; o >>= 1)
                    contrib += __shfl_down_sync(0xffffffffu, contrib, o);
                run += __shfl_sync(0xffffffffu, contrib, 0);
                if (incs) break;
                p -= 32;
            }
            if (lane == 0) {
                sbase = run;
                atomicExch(&stArr[tile], FLAG_INC | (unsigned)(run + cnt));
            }
        }
    }
    __syncthreads();

    const int base = sbase;
    float* dst = out + (size_t)b * NPTS * 6;

    // --- dense stable write: thread j handles the j-th valid row ---
    for (int j = tid; j < cnt; j += THREADS) {
        // smallest w with sscan[w] > j
        int lo = 0, hi = WORDS - 1;
#pragma unroll
        for (int s = 0; s < 6; s++) {
            const int mid = (lo + hi) >> 1;
            if (sscan[mid] > j) hi = mid; else lo = mid + 1;
        }
        const int w = lo;
        const int prior = w ? sscan[w - 1] : 0;
        const int r = j - prior;
        const int bit = __fns(sw[w], 0, r + 1);
        const int idx = p0 + w * 32 + bit;

        const float2* row = (const float2*)(src + (size_t)idx * 6);  // L2 hit
        const float2 a = row[0], c = row[1], d = row[2];
        float2* o = (float2*)(dst + (size_t)(base + j) * 6);
        __stcs(&o[0], a);
        __stcs(&o[1], c);
        __stcs(&o[2], d);
    }

    // --- fused tail zeroing ---
    // Exclusive invalid-prefix of this tile = p0 - base; this tile's invalid
    // count = TILE - cnt. Zero output rows
    // [NPTS - inv_prefix - inv, NPTS - inv_prefix); disjoint across tiles,
    // union = [total, NPTS).
    const int inv = TILE - cnt;
    if (inv > 0) {
        const int inv_prefix = p0 - base;
        const int row0 = NPTS - inv_prefix - inv;
        float2* z2 = (float2*)(dst + (size_t)row0 * 6);
        const int n2 = inv * 3;                  // float2 count
        const float2 z = make_float2(0.0f, 0.0f);
        for (int i = tid; i < n2; i += THREADS) __stcs(&z2[i], z);
    }
}

// ---------------------------------------------------------------------------
extern "C" void kernel_launch(void* const* d_in, const int* in_sizes, int n_in,
                              void* d_out, int out_size)
{
    const float* pc = (const float*)d_in[0];   // (32, 131072, 6)
    const float* tt = (const float*)d_in[1];   // (32, 4, 4)
    float* out = (float*)d_out;

    k_init<<<8, THREADS>>>();
    dim3 gc(NTILES, BATCH);
    k_compact<<<gc, THREADS>>>(pc, tt, out);
}